// round 15
// baseline (speedup 1.0000x reference)
#include <cuda_runtime.h>
#include <cuda_bf16.h>
#include <cuda_fp16.h>
#include <cstdint>

// Problem constants (fixed by the dataset)
#define NN 50000
#define EE 500000
#define DD 64      // node feature dim (== hidden dim H)
#define KK 4       // edge feature dim
#define HH 64      // hidden
#define CC 40      // classes
#define PCOLS 256  // K*H

#define GEMM_BLOCKS ((NN + 127) / 128)        // 391
#define EDGES_PER_GEMM_BLOCK 1280             // 391*1280 = 500480 >= EE

// ---------------------------------------------------------------------------
// Scratch (__device__ globals are the allowed scratch mechanism)
// P layout: per node, 32 x uint4. uint4 index h2 (=h/2) holds 4 half2s,
// one per k: entry [h2][k] = (P[k*64+2*h2], P[k*64+2*h2+1]).
// => lane l loads its whole per-edge operand as ONE uint4.
// ---------------------------------------------------------------------------
__device__ uint4 g_P[NN * 32];        // per-node P, (h-pair, k)-ordered fp16
__device__ float g_h[NN * HH];        // hidden node features between layers
__device__ int   g_cnt[NN];           // in-degree
__device__ int   g_off[NN];           // CSR row offsets (by dst)
__device__ int   g_rank[EE];          // within-dst rank of each edge
__device__ int2  g_csr[EE];           // (src, edge-id) per sorted slot
__device__ uint32_t g_Bhi1[8192];     // packed W1 (bf16x2 hi)
__device__ uint32_t g_Blo1[8192];     // packed W1 (bf16x2 lo)

// ---------------------------------------------------------------------------
// Split-bf16 packing helper (x = hi + lo, each bf16)
// ---------------------------------------------------------------------------
__device__ __forceinline__ void split_pack(float x, float y, uint32_t& hi, uint32_t& lo) {
    __nv_bfloat16 xh = __float2bfloat16(x);
    __nv_bfloat16 yh = __float2bfloat16(y);
    __nv_bfloat16 xl = __float2bfloat16(x - __bfloat162float(xh));
    __nv_bfloat16 yl = __float2bfloat16(y - __bfloat162float(yh));
    hi = ((uint32_t)__bfloat16_as_ushort(yh) << 16) | (uint32_t)__bfloat16_as_ushort(xh);
    lo = ((uint32_t)__bfloat16_as_ushort(yl) << 16) | (uint32_t)__bfloat16_as_ushort(xl);
}

// ---------------------------------------------------------------------------
// Scan (block 0) + packW1 (blocks 1..8). blockDim = 1024.
// ---------------------------------------------------------------------------
__global__ __launch_bounds__(1024) void scan_packW1_kernel(
    const int* __restrict__ cnt, int* __restrict__ off, int N,
    const float* __restrict__ W1,
    uint32_t* __restrict__ Bhi1, uint32_t* __restrict__ Blo1)
{
    if (blockIdx.x > 0) {
        int t = (blockIdx.x - 1) * 1024 + threadIdx.x;   // 0..8191
        if (t < 8192) {
            int n = t >> 5;
            int dd = t & 31;
            int ke = n >> 6, h = n & 63;
            float x = W1[(ke * 64 + 2 * dd) * 64 + h];
            float y = W1[(ke * 64 + 2 * dd + 1) * 64 + h];
            uint32_t hi, lo;
            split_pack(x, y, hi, lo);
            Bhi1[t] = hi;
            Blo1[t] = lo;
        }
        return;
    }
    __shared__ int ts[1024];
    const int tid = threadIdx.x;
    const int CH = (N + 1023) / 1024;
    int b = tid * CH;
    int e = b + CH; if (e > N) e = N;
    int s = 0;
    for (int i = b; i < e; i++) s += cnt[i];
    ts[tid] = s;
    __syncthreads();
    for (int d = 1; d < 1024; d <<= 1) {
        int v = (tid >= d) ? ts[tid - d] : 0;
        __syncthreads();
        ts[tid] += v;
        __syncthreads();
    }
    int run = (tid == 0) ? 0 : ts[tid - 1];
    for (int i = b; i < e; i++) {
        off[i] = run;
        run += cnt[i];
    }
}

// ---------------------------------------------------------------------------
// Scatter (no atomics): slot = off[dst[e]] + rank[e]; write (src, e).
// ---------------------------------------------------------------------------
__global__ void scatter_kernel(
    const int* __restrict__ src, const int* __restrict__ dst,
    const int* __restrict__ off, const int* __restrict__ rank,
    int2* __restrict__ csr, int E)
{
    int e = blockIdx.x * blockDim.x + threadIdx.x;
    if (e >= E) return;
    int p = off[dst[e]] + rank[e];
    csr[p] = make_int2(src[e], e);
}

// ---------------------------------------------------------------------------
// Tensor-core GEMM: P[N,256] = A[N,64] @ B[64,256], output fp16 in
// (h-pair, k)-ordered layout, SMEM-staged coalesced epilogue.
// Split-bf16 (hi+lo), 3 MMAs per product pair -> fp32-level accuracy.
// Block: 256 thr (8 warps), tile M=128, N=256. Warp tile 32x128.
// Layer-0 variant (Wraw != null): packs B from W0 inline AND processes a
// 1280-edge histogram slice (rank/cnt) — hides the CSR hist behind the GEMM.
// Layer-1 variant (Wraw == null): copies pre-packed B.
// ---------------------------------------------------------------------------
#define GSTRIDE 36   // u32 row stride: rows shift 4 banks -> ldmatrix conflict-free
#define SM_AHI 0
#define SM_ALO (128 * GSTRIDE)
#define SM_BHI (2 * 128 * GSTRIDE)
#define SM_BLO (2 * 128 * GSTRIDE + 256 * GSTRIDE)
#define SM_TOT (2 * 128 * GSTRIDE + 2 * 256 * GSTRIDE)   // 27648 u32 = 108KB
#define SSTRIDE 136  // stage row stride in u32 (16B-aligned, 8-bank row shift)

__device__ __forceinline__ void ldsm_x4(uint32_t* r, uint32_t addr) {
    asm volatile("ldmatrix.sync.aligned.m8n8.x4.shared.b16 {%0,%1,%2,%3}, [%4];"
                 : "=r"(r[0]), "=r"(r[1]), "=r"(r[2]), "=r"(r[3]) : "r"(addr));
}

#define MMA_BF16(C, A, B0, B1) asm volatile( \
    "mma.sync.aligned.m16n8k16.row.col.f32.bf16.bf16.f32 " \
    "{%0,%1,%2,%3}, {%4,%5,%6,%7}, {%8,%9}, {%0,%1,%2,%3};\n" \
    : "+f"((C)[0]), "+f"((C)[1]), "+f"((C)[2]), "+f"((C)[3]) \
    : "r"((A)[0]), "r"((A)[1]), "r"((A)[2]), "r"((A)[3]), "r"(B0), "r"(B1))

__global__ __launch_bounds__(256, 1) void gemm_tc_kernel(
    const float* __restrict__ A,
    const uint32_t* __restrict__ Bhi_g, const uint32_t* __restrict__ Blo_g,
    const float* __restrict__ Wraw,           // non-null => layer-0 fused mode
    const int* __restrict__ dst, int* __restrict__ cnt, int* __restrict__ rank,
    uint4* __restrict__ Pout, int Nrows)
{
    extern __shared__ uint32_t smTC[];

    const int tid = threadIdx.x;
    const int row0 = blockIdx.x * 128;

    // Fill B smem: inline-pack from Wraw (layer 0) or copy pre-packed (layer 1)
    if (Wraw) {
        const int ke = tid >> 6;
        const int h = tid & 63;
        #pragma unroll 4
        for (int dd = 0; dd < 32; dd++) {
            float x = Wraw[(ke * 64 + 2 * dd) * 64 + h];       // coalesced in h
            float y = Wraw[(ke * 64 + 2 * dd + 1) * 64 + h];
            uint32_t hi, lo;
            split_pack(x, y, hi, lo);
            smTC[SM_BHI + tid * GSTRIDE + dd] = hi;            // n == tid
            smTC[SM_BLO + tid * GSTRIDE + dd] = lo;
        }
    } else {
        const uint4* bh = reinterpret_cast<const uint4*>(Bhi_g);
        const uint4* bl = reinterpret_cast<const uint4*>(Blo_g);
        #pragma unroll
        for (int it = 0; it < 8; it++) {
            int i = tid + it * 256;          // 0..2047, n = i>>3, c = i&7
            int n = i >> 3, c = i & 7;
            *reinterpret_cast<uint4*>(&smTC[SM_BHI + n * GSTRIDE + c * 4]) = bh[i];
            *reinterpret_cast<uint4*>(&smTC[SM_BLO + n * GSTRIDE + c * 4]) = bl[i];
        }
    }
    // Pack A tile (128 rows x 32 pairs) from fp32
    #pragma unroll
    for (int it = 0; it < 16; it++) {
        int idx = tid + it * 256;            // 0..4095
        int row = idx >> 5;
        int dd = idx & 31;
        float2 v = make_float2(0.f, 0.f);
        if (row0 + row < Nrows)
            v = reinterpret_cast<const float2*>(A)[(size_t)(row0 + row) * 32 + dd];
        uint32_t hi, lo;
        split_pack(v.x, v.y, hi, lo);
        smTC[SM_AHI + row * GSTRIDE + dd] = hi;
        smTC[SM_ALO + row * GSTRIDE + dd] = lo;
    }

    // Fused histogram slice (layer 0 only): 1280 edges per block, MLP-5.
    if (Wraw) {
        int e0 = blockIdx.x * EDGES_PER_GEMM_BLOCK;
        #pragma unroll
        for (int q = 0; q < 5; q++) {
            int e = e0 + q * 256 + tid;
            if (e < EE) rank[e] = atomicAdd(&cnt[dst[e]], 1);
        }
    }
    __syncthreads();

    const int w = tid >> 5;
    const int lane = tid & 31;
    const int g = lane >> 2;      // groupID
    const int ctid = lane & 3;    // thread in group
    const int wm = w >> 1;        // 0..3 -> row base wm*32
    const int wn = w & 1;         // 0..1 -> col base wn*128

    const uint32_t sb = (uint32_t)__cvta_generic_to_shared(smTC);
    const int aRow = wm * 32 + (lane & 15);
    const int aCol = (lane >> 4) << 2;
    const uint32_t aHi = sb + (SM_AHI + aRow * GSTRIDE + aCol) * 4;
    const uint32_t aLo = sb + (SM_ALO + aRow * GSTRIDE + aCol) * 4;
    const int bRow = wn * 128 + ((lane >> 4) << 3) + (lane & 7);
    const int bCol = ((lane >> 3) & 1) << 2;
    const uint32_t bHi = sb + (SM_BHI + bRow * GSTRIDE + bCol) * 4;
    const uint32_t bLo = sb + (SM_BLO + bRow * GSTRIDE + bCol) * 4;

    float acc[2][16][4];
    #pragma unroll
    for (int mt = 0; mt < 2; mt++)
        #pragma unroll
        for (int nt = 0; nt < 16; nt++)
            #pragma unroll
            for (int q = 0; q < 4; q++) acc[mt][nt][q] = 0.f;

    #pragma unroll
    for (int ks = 0; ks < 4; ks++) {
        const uint32_t koff = ks * 8 * 4;
        uint32_t ah[2][4], al[2][4];
        ldsm_x4(ah[0], aHi + koff);
        ldsm_x4(ah[1], aHi + 16 * GSTRIDE * 4 + koff);
        ldsm_x4(al[0], aLo + koff);
        ldsm_x4(al[1], aLo + 16 * GSTRIDE * 4 + koff);
        #pragma unroll
        for (int nt2 = 0; nt2 < 8; nt2++) {
            uint32_t bh[4], bl[4];
            ldsm_x4(bh, bHi + nt2 * 16 * GSTRIDE * 4 + koff);
            ldsm_x4(bl, bLo + nt2 * 16 * GSTRIDE * 4 + koff);
            #pragma unroll
            for (int mt = 0; mt < 2; mt++) {
                MMA_BF16(acc[mt][2 * nt2],     ah[mt], bh[0], bh[1]);
                MMA_BF16(acc[mt][2 * nt2],     ah[mt], bl[0], bl[1]);
                MMA_BF16(acc[mt][2 * nt2],     al[mt], bh[0], bh[1]);
                MMA_BF16(acc[mt][2 * nt2 + 1], ah[mt], bh[2], bh[3]);
                MMA_BF16(acc[mt][2 * nt2 + 1], ah[mt], bl[2], bl[3]);
                MMA_BF16(acc[mt][2 * nt2 + 1], al[mt], bh[2], bh[3]);
            }
        }
    }

    // Epilogue: stage permuted half2s in smem (reuse smTC), then coalesced
    // uint4 row stores to global.
    __syncthreads();   // done reading A/B tiles
    #pragma unroll
    for (int mt = 0; mt < 2; mt++) {
        #pragma unroll
        for (int nt = 0; nt < 16; nt++) {
            int rloc = wm * 32 + mt * 16 + g;
            int col = wn * 128 + nt * 8 + 2 * ctid;  // 0..255, even
            int ke = col >> 6;
            int h2 = (col & 63) >> 1;
            int pidx = h2 * 4 + ke;
            __half2 v0 = __floats2half2_rn(acc[mt][nt][0], acc[mt][nt][1]);
            __half2 v1 = __floats2half2_rn(acc[mt][nt][2], acc[mt][nt][3]);
            smTC[rloc * SSTRIDE + pidx] = *reinterpret_cast<uint32_t*>(&v0);
            smTC[(rloc + 8) * SSTRIDE + pidx] = *reinterpret_cast<uint32_t*>(&v1);
        }
    }
    __syncthreads();
    // Coalesced copy out: 128 rows x 32 uint4
    #pragma unroll
    for (int it = 0; it < 16; it++) {
        int i = tid + it * 256;          // 0..4095
        int r = i >> 5, c = i & 31;
        if (row0 + r < Nrows)
            Pout[(size_t)(row0 + r) * 32 + c] =
                *reinterpret_cast<uint4*>(&smTC[r * SSTRIDE + c * 4]);
    }
}

// ---------------------------------------------------------------------------
// Consumer: warp = node, lane owns 2 h-cols (h = 2*lane, 2*lane+1).
// Per edge: 1 uniform csr load + 1 uniform ev load + ONE uint4 P load/lane.
// Unroll-8 tile with all loads hoisted (8 x 512B gathers in flight).
// ---------------------------------------------------------------------------
__device__ __forceinline__ void edge_fma(
    float4 ev, uint4 pk, float2 b2, float& ax, float& ay)
{
    const __half2* h2p = reinterpret_cast<const __half2*>(&pk);
    float2 p0 = __half22float2(h2p[0]);   // k=0
    float2 p1 = __half22float2(h2p[1]);   // k=1
    float2 p2 = __half22float2(h2p[2]);   // k=2
    float2 p3 = __half22float2(h2p[3]);   // k=3
    float vx = b2.x + ev.x * p0.x + ev.y * p1.x + ev.z * p2.x + ev.w * p3.x;
    float vy = b2.y + ev.x * p0.y + ev.y * p1.y + ev.z * p2.y + ev.w * p3.y;
    ax += fmaxf(vx, 0.f);
    ay += fmaxf(vy, 0.f);
}

__device__ __forceinline__ void consume_node(
    const uint4* __restrict__ P, const int2* __restrict__ csr,
    const float4* __restrict__ cef, int o, int deg, int lane,
    float2 b2, float& rx, float& ry)
{
    float ax = 0.f, ay = 0.f;
    int j = 0;
    for (; j + 8 <= deg; j += 8) {
        int2 c[8];
        #pragma unroll
        for (int q = 0; q < 8; q++) c[q] = csr[o + j + q];
        float4 ev[8];
        uint4 p[8];
        #pragma unroll
        for (int q = 0; q < 8; q++) ev[q] = cef[c[q].y];
        #pragma unroll
        for (int q = 0; q < 8; q++) p[q] = P[(size_t)c[q].x * 32 + lane];
        #pragma unroll
        for (int q = 0; q < 8; q++) edge_fma(ev[q], p[q], b2, ax, ay);
    }
    for (; j + 4 <= deg; j += 4) {
        int2 c[4];
        #pragma unroll
        for (int q = 0; q < 4; q++) c[q] = csr[o + j + q];
        float4 ev[4];
        uint4 p[4];
        #pragma unroll
        for (int q = 0; q < 4; q++) ev[q] = cef[c[q].y];
        #pragma unroll
        for (int q = 0; q < 4; q++) p[q] = P[(size_t)c[q].x * 32 + lane];
        #pragma unroll
        for (int q = 0; q < 4; q++) edge_fma(ev[q], p[q], b2, ax, ay);
    }
    for (; j < deg; j++) {
        int2 c = csr[o + j];
        float4 ev = cef[c.y];
        uint4 p = P[(size_t)c.x * 32 + lane];
        edge_fma(ev, p, b2, ax, ay);
    }
    float inv = 1.0f / fmaxf((float)deg, 1.0f);
    rx = fmaxf(ax * inv, 0.f);
    ry = fmaxf(ay * inv, 0.f);
}

// ---------------------------------------------------------------------------
// Layer consumer: h = relu(mean(messages)). One warp per node.
// ---------------------------------------------------------------------------
__global__ __launch_bounds__(256) void layer_kernel(
    const uint4* __restrict__ P, const int* __restrict__ off,
    const int* __restrict__ cnt, const int2* __restrict__ csr,
    const float4* __restrict__ cef, const float* __restrict__ bias,
    float* __restrict__ hout, int N)
{
    int warp = (blockIdx.x * blockDim.x + threadIdx.x) >> 5;
    int lane = threadIdx.x & 31;
    if (warp >= N) return;
    float2 b2 = reinterpret_cast<const float2*>(bias)[lane];
    float rx, ry;
    consume_node(P, csr, cef, off[warp], cnt[warp], lane, b2, rx, ry);
    reinterpret_cast<float2*>(hout)[(size_t)warp * 32 + lane] = make_float2(rx, ry);
}

// ---------------------------------------------------------------------------
// Layer-2 consumer fused with final FC: out[n] = h2[n] @ Wfc + bfc
// ---------------------------------------------------------------------------
__global__ __launch_bounds__(256) void layer_fc_kernel(
    const uint4* __restrict__ P, const int* __restrict__ off,
    const int* __restrict__ cnt, const int2* __restrict__ csr,
    const float4* __restrict__ cef, const float* __restrict__ bias,
    const float* __restrict__ Wfc, const float* __restrict__ bfc,
    float* __restrict__ out, int N)
{
    __shared__ float Wf[64 * 40];
    __shared__ float bf[40];
    __shared__ float hrow[8][64];

    const int tid = threadIdx.x;
    for (int i = tid; i < 64 * 40; i += 256) Wf[i] = Wfc[i];
    if (tid < 40) bf[tid] = bfc[tid];
    __syncthreads();

    const int wwarp = tid >> 5;
    const int lane = tid & 31;
    const int n = blockIdx.x * 8 + wwarp;

    float rx = 0.f, ry = 0.f;
    if (n < N) {
        float2 b2 = reinterpret_cast<const float2*>(bias)[lane];
        consume_node(P, csr, cef, off[n], cnt[n], lane, b2, rx, ry);
    }
    hrow[wwarp][2 * lane] = rx;
    hrow[wwarp][2 * lane + 1] = ry;
    __syncwarp();

    if (n < N) {
        float a0 = bf[lane];
        float a1 = (lane < 8) ? bf[32 + lane] : 0.f;
        #pragma unroll
        for (int h = 0; h < 64; h++) {
            float hv = hrow[wwarp][h];
            a0 += hv * Wf[h * 40 + lane];
            if (lane < 8) a1 += hv * Wf[h * 40 + 32 + lane];
        }
        out[(size_t)n * 40 + lane] = a0;
        if (lane < 8) out[(size_t)n * 40 + 32 + lane] = a1;
    }
}

// ---------------------------------------------------------------------------
extern "C" void kernel_launch(void* const* d_in, const int* in_sizes, int n_in,
                              void* d_out, int out_size)
{
    const float* node_features = (const float*)d_in[0];
    const float* edge_features = (const float*)d_in[1]; // [2, E, 4]
    const int*   src           = (const int*)d_in[2];
    const int*   dst           = (const int*)d_in[3];
    const float* W0            = (const float*)d_in[4];
    const float* b0            = (const float*)d_in[5];
    const float* W1            = (const float*)d_in[6];
    const float* b1            = (const float*)d_in[7];
    const float* Wfc           = (const float*)d_in[8];
    const float* bfc           = (const float*)d_in[9];
    float* out = (float*)d_out;

    uint4 *Pp;
    float *hp;
    int *cntp, *offp, *rkp;
    int2 *csrp;
    uint32_t *bh1p, *bl1p;
    cudaGetSymbolAddress((void**)&Pp, g_P);
    cudaGetSymbolAddress((void**)&hp, g_h);
    cudaGetSymbolAddress((void**)&cntp, g_cnt);
    cudaGetSymbolAddress((void**)&offp, g_off);
    cudaGetSymbolAddress((void**)&rkp, g_rank);
    cudaGetSymbolAddress((void**)&csrp, g_csr);
    cudaGetSymbolAddress((void**)&bh1p, g_Bhi1);
    cudaGetSymbolAddress((void**)&bl1p, g_Blo1);

    const int tc_smem = SM_TOT * (int)sizeof(uint32_t); // 108KB (>= stage 69.6KB)
    cudaFuncSetAttribute(gemm_tc_kernel, cudaFuncAttributeMaxDynamicSharedMemorySize, tc_smem);

    const int layer_blocks = (NN + 7) / 8;   // 8 warps/block, warp per node

    const float4* cef0 = (const float4*)edge_features;
    const float4* cef1 = (const float4*)(edge_features + (size_t)EE * KK);

    // Zero degree counters; then layer-0 GEMM with fused histogram + inline
    // W0 packing (hides the CSR hist behind the GEMM).
    cudaMemsetAsync(cntp, 0, NN * sizeof(int), 0);
    gemm_tc_kernel<<<GEMM_BLOCKS, 256, tc_smem>>>(
        node_features, nullptr, nullptr, W0, dst, cntp, rkp, Pp, NN);

    // Scan (+ fused W1 packing), then scatter.
    scan_packW1_kernel<<<9, 1024>>>(cntp, offp, NN, W1, bh1p, bl1p);
    scatter_kernel<<<(EE + 255) / 256, 256>>>(src, dst, offp, rkp, csrp, EE);

    // Layer 0 consumer
    layer_kernel<<<layer_blocks, 256>>>(Pp, offp, cntp, csrp, cef0, b0, hp, NN);

    // Layer 1 GEMM (pre-packed W1) + fused-FC consumer
    gemm_tc_kernel<<<GEMM_BLOCKS, 256, tc_smem>>>(
        hp, bh1p, bl1p, nullptr, nullptr, nullptr, nullptr, Pp, NN);
    layer_fc_kernel<<<layer_blocks, 256>>>(Pp, offp, cntp, csrp, cef1, b1, Wfc, bfc, out, NN);
}

// round 16
// speedup vs baseline: 1.0677x; 1.0677x over previous
#include <cuda_runtime.h>
#include <cuda_bf16.h>
#include <cuda_fp16.h>
#include <cstdint>

// Problem constants (fixed by the dataset)
#define NN 50000
#define EE 500000
#define DD 64      // node feature dim (== hidden dim H)
#define KK 4       // edge feature dim
#define HH 64      // hidden
#define CC 40      // classes
#define PCOLS 256  // K*H

// ---------------------------------------------------------------------------
// Scratch (__device__ globals are the allowed scratch mechanism)
// P layout: per node, 32 x uint4. uint4 index h2 (=h/2) holds 4 half2s,
// one per k: entry [h2][k] = (P[k*64+2*h2], P[k*64+2*h2+1]).
// => lane l loads its whole per-edge operand as ONE uint4.
// ---------------------------------------------------------------------------
__device__ uint4 g_P[NN * 32];        // per-node P, (h-pair, k)-ordered fp16
__device__ float g_h[NN * HH];        // hidden node features between layers
__device__ int   g_cnt[NN];           // in-degree
__device__ int   g_off[NN];           // CSR row offsets (by dst)
__device__ int   g_rank[EE];          // within-dst rank of each edge
__device__ int2  g_csr[EE];           // (src, edge-id) per sorted slot
__device__ uint32_t g_Bhi[2 * 8192];  // packed W (bf16x2 hi), [layer][n*32+dd]
__device__ uint32_t g_Blo[2 * 8192];  // packed W (bf16x2 lo)

// ---------------------------------------------------------------------------
// Split-bf16 packing helper (x = hi + lo, each bf16)
// ---------------------------------------------------------------------------
__device__ __forceinline__ void split_pack(float x, float y, uint32_t& hi, uint32_t& lo) {
    __nv_bfloat16 xh = __float2bfloat16(x);
    __nv_bfloat16 yh = __float2bfloat16(y);
    __nv_bfloat16 xl = __float2bfloat16(x - __bfloat162float(xh));
    __nv_bfloat16 yl = __float2bfloat16(y - __bfloat162float(yh));
    hi = ((uint32_t)__bfloat16_as_ushort(yh) << 16) | (uint32_t)__bfloat16_as_ushort(xh);
    lo = ((uint32_t)__bfloat16_as_ushort(yl) << 16) | (uint32_t)__bfloat16_as_ushort(xl);
}

// ---------------------------------------------------------------------------
// Fused: histogram of dst (records within-node rank) + W packing (R14 form).
// ---------------------------------------------------------------------------
#define HPW_TOTAL (EE + 2 * 8192)
__global__ void hist_packW_kernel(
    const int* __restrict__ dst, int* __restrict__ cnt, int* __restrict__ rank,
    const float* __restrict__ W0, const float* __restrict__ W1,
    uint32_t* __restrict__ Bhi, uint32_t* __restrict__ Blo)
{
    int t = blockIdx.x * blockDim.x + threadIdx.x;
    if (t < EE) {
        rank[t] = atomicAdd(&cnt[dst[t]], 1);
    } else if (t < HPW_TOTAL) {
        int idx = t - EE;                 // 0 .. 16383
        int l = idx >> 13;
        int r = idx & 8191;
        int n = r >> 5;
        int dd = r & 31;
        const float* W = l ? W1 : W0;
        int ke = n >> 6, h = n & 63;
        float x = W[(ke * 64 + 2 * dd) * 64 + h];
        float y = W[(ke * 64 + 2 * dd + 1) * 64 + h];
        uint32_t hi, lo;
        split_pack(x, y, hi, lo);
        Bhi[idx] = hi;
        Blo[idx] = lo;
    }
}

// ---------------------------------------------------------------------------
// Exclusive prefix sum over cnt -> off. Single block, 1024 thr.
// ---------------------------------------------------------------------------
__global__ __launch_bounds__(1024) void scan_kernel(
    const int* __restrict__ cnt, int* __restrict__ off, int N)
{
    __shared__ int ts[1024];
    const int tid = threadIdx.x;
    const int CH = (N + 1023) / 1024;
    int b = tid * CH;
    int e = b + CH; if (e > N) e = N;
    int s = 0;
    for (int i = b; i < e; i++) s += cnt[i];
    ts[tid] = s;
    __syncthreads();
    for (int d = 1; d < 1024; d <<= 1) {
        int v = (tid >= d) ? ts[tid - d] : 0;
        __syncthreads();
        ts[tid] += v;
        __syncthreads();
    }
    int run = (tid == 0) ? 0 : ts[tid - 1];
    for (int i = b; i < e; i++) {
        off[i] = run;
        run += cnt[i];
    }
}

// ---------------------------------------------------------------------------
// Scatter (no atomics): slot = off[dst[e]] + rank[e]; write (src, e).
// ---------------------------------------------------------------------------
__global__ void scatter_kernel(
    const int* __restrict__ src, const int* __restrict__ dst,
    const int* __restrict__ off, const int* __restrict__ rank,
    int2* __restrict__ csr, int E)
{
    int e = blockIdx.x * blockDim.x + threadIdx.x;
    if (e >= E) return;
    int p = off[dst[e]] + rank[e];
    csr[p] = make_int2(src[e], e);
}

// ---------------------------------------------------------------------------
// Tensor-core GEMM: P[N,256] = A[N,64] @ B[64,256], output fp16 in
// (h-pair, k)-ordered layout, SMEM-staged coalesced epilogue. (R14 form.)
// Split-bf16 (hi+lo), 3 MMAs per product pair -> fp32-level accuracy.
// Block: 256 thr (8 warps), tile M=128, N=256. Warp tile 32x128.
// ---------------------------------------------------------------------------
#define GSTRIDE 36   // u32 row stride: rows shift 4 banks -> ldmatrix conflict-free
#define SM_AHI 0
#define SM_ALO (128 * GSTRIDE)
#define SM_BHI (2 * 128 * GSTRIDE)
#define SM_BLO (2 * 128 * GSTRIDE + 256 * GSTRIDE)
#define SM_TOT (2 * 128 * GSTRIDE + 2 * 256 * GSTRIDE)   // 27648 u32 = 108KB
#define SSTRIDE 136  // stage row stride in u32 (16B-aligned, 8-bank row shift)

__device__ __forceinline__ void ldsm_x4(uint32_t* r, uint32_t addr) {
    asm volatile("ldmatrix.sync.aligned.m8n8.x4.shared.b16 {%0,%1,%2,%3}, [%4];"
                 : "=r"(r[0]), "=r"(r[1]), "=r"(r[2]), "=r"(r[3]) : "r"(addr));
}

#define MMA_BF16(C, A, B0, B1) asm volatile( \
    "mma.sync.aligned.m16n8k16.row.col.f32.bf16.bf16.f32 " \
    "{%0,%1,%2,%3}, {%4,%5,%6,%7}, {%8,%9}, {%0,%1,%2,%3};\n" \
    : "+f"((C)[0]), "+f"((C)[1]), "+f"((C)[2]), "+f"((C)[3]) \
    : "r"((A)[0]), "r"((A)[1]), "r"((A)[2]), "r"((A)[3]), "r"(B0), "r"(B1))

__global__ __launch_bounds__(256, 1) void gemm_tc_kernel(
    const float* __restrict__ A,
    const uint32_t* __restrict__ Bhi_g, const uint32_t* __restrict__ Blo_g,
    uint4* __restrict__ Pout, int Nrows)   // Pout: uint4 view, row stride 32
{
    extern __shared__ uint32_t smTC[];

    const int tid = threadIdx.x;
    const int row0 = blockIdx.x * 128;

    // Copy pre-packed B into smem (uint4)
    {
        const uint4* bh = reinterpret_cast<const uint4*>(Bhi_g);
        const uint4* bl = reinterpret_cast<const uint4*>(Blo_g);
        #pragma unroll
        for (int it = 0; it < 8; it++) {
            int i = tid + it * 256;          // 0..2047, n = i>>3, c = i&7
            int n = i >> 3, c = i & 7;
            *reinterpret_cast<uint4*>(&smTC[SM_BHI + n * GSTRIDE + c * 4]) = bh[i];
            *reinterpret_cast<uint4*>(&smTC[SM_BLO + n * GSTRIDE + c * 4]) = bl[i];
        }
    }
    // Pack A tile (128 rows x 32 pairs) from fp32
    #pragma unroll
    for (int it = 0; it < 16; it++) {
        int idx = tid + it * 256;            // 0..4095
        int row = idx >> 5;
        int dd = idx & 31;
        float2 v = make_float2(0.f, 0.f);
        if (row0 + row < Nrows)
            v = reinterpret_cast<const float2*>(A)[(size_t)(row0 + row) * 32 + dd];
        uint32_t hi, lo;
        split_pack(v.x, v.y, hi, lo);
        smTC[SM_AHI + row * GSTRIDE + dd] = hi;
        smTC[SM_ALO + row * GSTRIDE + dd] = lo;
    }
    __syncthreads();

    const int w = tid >> 5;
    const int lane = tid & 31;
    const int g = lane >> 2;      // groupID
    const int ctid = lane & 3;    // thread in group
    const int wm = w >> 1;        // 0..3 -> row base wm*32
    const int wn = w & 1;         // 0..1 -> col base wn*128

    const uint32_t sb = (uint32_t)__cvta_generic_to_shared(smTC);
    const int aRow = wm * 32 + (lane & 15);
    const int aCol = (lane >> 4) << 2;
    const uint32_t aHi = sb + (SM_AHI + aRow * GSTRIDE + aCol) * 4;
    const uint32_t aLo = sb + (SM_ALO + aRow * GSTRIDE + aCol) * 4;
    const int bRow = wn * 128 + ((lane >> 4) << 3) + (lane & 7);
    const int bCol = ((lane >> 3) & 1) << 2;
    const uint32_t bHi = sb + (SM_BHI + bRow * GSTRIDE + bCol) * 4;
    const uint32_t bLo = sb + (SM_BLO + bRow * GSTRIDE + bCol) * 4;

    float acc[2][16][4];
    #pragma unroll
    for (int mt = 0; mt < 2; mt++)
        #pragma unroll
        for (int nt = 0; nt < 16; nt++)
            #pragma unroll
            for (int q = 0; q < 4; q++) acc[mt][nt][q] = 0.f;

    #pragma unroll
    for (int ks = 0; ks < 4; ks++) {
        const uint32_t koff = ks * 8 * 4;
        uint32_t ah[2][4], al[2][4];
        ldsm_x4(ah[0], aHi + koff);
        ldsm_x4(ah[1], aHi + 16 * GSTRIDE * 4 + koff);
        ldsm_x4(al[0], aLo + koff);
        ldsm_x4(al[1], aLo + 16 * GSTRIDE * 4 + koff);
        #pragma unroll
        for (int nt2 = 0; nt2 < 8; nt2++) {
            uint32_t bh[4], bl[4];
            ldsm_x4(bh, bHi + nt2 * 16 * GSTRIDE * 4 + koff);
            ldsm_x4(bl, bLo + nt2 * 16 * GSTRIDE * 4 + koff);
            #pragma unroll
            for (int mt = 0; mt < 2; mt++) {
                MMA_BF16(acc[mt][2 * nt2],     ah[mt], bh[0], bh[1]);
                MMA_BF16(acc[mt][2 * nt2],     ah[mt], bl[0], bl[1]);
                MMA_BF16(acc[mt][2 * nt2],     al[mt], bh[0], bh[1]);
                MMA_BF16(acc[mt][2 * nt2 + 1], ah[mt], bh[2], bh[3]);
                MMA_BF16(acc[mt][2 * nt2 + 1], ah[mt], bl[2], bl[3]);
                MMA_BF16(acc[mt][2 * nt2 + 1], al[mt], bh[2], bh[3]);
            }
        }
    }

    // Epilogue: stage permuted half2s in smem (reuse smTC), then coalesced
    // uint4 row stores to global.
    __syncthreads();   // done reading A/B tiles
    #pragma unroll
    for (int mt = 0; mt < 2; mt++) {
        #pragma unroll
        for (int nt = 0; nt < 16; nt++) {
            int rloc = wm * 32 + mt * 16 + g;
            int col = wn * 128 + nt * 8 + 2 * ctid;  // 0..255, even
            int ke = col >> 6;
            int h2 = (col & 63) >> 1;
            int pidx = h2 * 4 + ke;
            __half2 v0 = __floats2half2_rn(acc[mt][nt][0], acc[mt][nt][1]);
            __half2 v1 = __floats2half2_rn(acc[mt][nt][2], acc[mt][nt][3]);
            smTC[rloc * SSTRIDE + pidx] = *reinterpret_cast<uint32_t*>(&v0);
            smTC[(rloc + 8) * SSTRIDE + pidx] = *reinterpret_cast<uint32_t*>(&v1);
        }
    }
    __syncthreads();
    // Coalesced copy out: 128 rows x 32 uint4
    #pragma unroll
    for (int it = 0; it < 16; it++) {
        int i = tid + it * 256;          // 0..4095
        int r = i >> 5, c = i & 31;
        if (row0 + r < Nrows)
            Pout[(size_t)(row0 + r) * 32 + c] =
                *reinterpret_cast<uint4*>(&smTC[r * SSTRIDE + c * 4]);
    }
}

// ---------------------------------------------------------------------------
// Consumer: warp = node, lane owns 2 h-cols (h = 2*lane, 2*lane+1).
// Per edge: 1 uniform csr load + 1 uniform ev load + ONE uint4 P load/lane.
// Half2 inner product (1 HMUL2 + 3 HFMA2), fp32 bias/relu/accumulate.
// Unroll-8 tile with all loads hoisted (8 x 512B gathers in flight).
// ---------------------------------------------------------------------------
__device__ __forceinline__ void edge_fma(
    const __half2 evh[4], uint4 pk, float2 b2, float& ax, float& ay)
{
    const __half2* p = reinterpret_cast<const __half2*>(&pk);
    __half2 m = __hmul2(evh[0], p[0]);
    m = __hfma2(evh[1], p[1], m);
    m = __hfma2(evh[2], p[2], m);
    m = __hfma2(evh[3], p[3], m);
    float2 f = __half22float2(m);
    ax += fmaxf(b2.x + f.x, 0.f);
    ay += fmaxf(b2.y + f.y, 0.f);
}

__device__ __forceinline__ void cvt_ev(float4 ev, __half2 evh[4]) {
    evh[0] = __float2half2_rn(ev.x);
    evh[1] = __float2half2_rn(ev.y);
    evh[2] = __float2half2_rn(ev.z);
    evh[3] = __float2half2_rn(ev.w);
}

__device__ __forceinline__ void consume_node(
    const uint4* __restrict__ P, const int2* __restrict__ csr,
    const float4* __restrict__ cef, int o, int deg, int lane,
    float2 b2, float& rx, float& ry)
{
    float ax = 0.f, ay = 0.f;
    int j = 0;
    for (; j + 8 <= deg; j += 8) {
        int2 c[8];
        #pragma unroll
        for (int q = 0; q < 8; q++) c[q] = csr[o + j + q];
        float4 ev[8];
        uint4 p[8];
        #pragma unroll
        for (int q = 0; q < 8; q++) ev[q] = cef[c[q].y];
        #pragma unroll
        for (int q = 0; q < 8; q++) p[q] = P[(size_t)c[q].x * 32 + lane];
        #pragma unroll
        for (int q = 0; q < 8; q++) {
            __half2 evh[4];
            cvt_ev(ev[q], evh);
            edge_fma(evh, p[q], b2, ax, ay);
        }
    }
    for (; j + 4 <= deg; j += 4) {
        int2 c[4];
        #pragma unroll
        for (int q = 0; q < 4; q++) c[q] = csr[o + j + q];
        float4 ev[4];
        uint4 p[4];
        #pragma unroll
        for (int q = 0; q < 4; q++) ev[q] = cef[c[q].y];
        #pragma unroll
        for (int q = 0; q < 4; q++) p[q] = P[(size_t)c[q].x * 32 + lane];
        #pragma unroll
        for (int q = 0; q < 4; q++) {
            __half2 evh[4];
            cvt_ev(ev[q], evh);
            edge_fma(evh, p[q], b2, ax, ay);
        }
    }
    for (; j < deg; j++) {
        int2 c = csr[o + j];
        float4 ev = cef[c.y];
        uint4 p = P[(size_t)c.x * 32 + lane];
        __half2 evh[4];
        cvt_ev(ev, evh);
        edge_fma(evh, p, b2, ax, ay);
    }
    float inv = 1.0f / fmaxf((float)deg, 1.0f);
    rx = fmaxf(ax * inv, 0.f);
    ry = fmaxf(ay * inv, 0.f);
}

// ---------------------------------------------------------------------------
// Layer consumer: h = relu(mean(messages)). One warp per node.
// ---------------------------------------------------------------------------
__global__ __launch_bounds__(256) void layer_kernel(
    const uint4* __restrict__ P, const int* __restrict__ off,
    const int* __restrict__ cnt, const int2* __restrict__ csr,
    const float4* __restrict__ cef, const float* __restrict__ bias,
    float* __restrict__ hout, int N)
{
    int warp = (blockIdx.x * blockDim.x + threadIdx.x) >> 5;
    int lane = threadIdx.x & 31;
    if (warp >= N) return;
    float2 b2 = reinterpret_cast<const float2*>(bias)[lane];
    float rx, ry;
    consume_node(P, csr, cef, off[warp], cnt[warp], lane, b2, rx, ry);
    reinterpret_cast<float2*>(hout)[(size_t)warp * 32 + lane] = make_float2(rx, ry);
}

// ---------------------------------------------------------------------------
// Layer-2 consumer fused with final FC: out[n] = h2[n] @ Wfc + bfc
// ---------------------------------------------------------------------------
__global__ __launch_bounds__(256) void layer_fc_kernel(
    const uint4* __restrict__ P, const int* __restrict__ off,
    const int* __restrict__ cnt, const int2* __restrict__ csr,
    const float4* __restrict__ cef, const float* __restrict__ bias,
    const float* __restrict__ Wfc, const float* __restrict__ bfc,
    float* __restrict__ out, int N)
{
    __shared__ float Wf[64 * 40];
    __shared__ float bf[40];
    __shared__ float hrow[8][64];

    const int tid = threadIdx.x;
    for (int i = tid; i < 64 * 40; i += 256) Wf[i] = Wfc[i];
    if (tid < 40) bf[tid] = bfc[tid];
    __syncthreads();

    const int wwarp = tid >> 5;
    const int lane = tid & 31;
    const int n = blockIdx.x * 8 + wwarp;

    float rx = 0.f, ry = 0.f;
    if (n < N) {
        float2 b2 = reinterpret_cast<const float2*>(bias)[lane];
        consume_node(P, csr, cef, off[n], cnt[n], lane, b2, rx, ry);
    }
    hrow[wwarp][2 * lane] = rx;
    hrow[wwarp][2 * lane + 1] = ry;
    __syncwarp();

    if (n < N) {
        float a0 = bf[lane];
        float a1 = (lane < 8) ? bf[32 + lane] : 0.f;
        #pragma unroll
        for (int h = 0; h < 64; h++) {
            float hv = hrow[wwarp][h];
            a0 += hv * Wf[h * 40 + lane];
            if (lane < 8) a1 += hv * Wf[h * 40 + 32 + lane];
        }
        out[(size_t)n * 40 + lane] = a0;
        if (lane < 8) out[(size_t)n * 40 + 32 + lane] = a1;
    }
}

// ---------------------------------------------------------------------------
extern "C" void kernel_launch(void* const* d_in, const int* in_sizes, int n_in,
                              void* d_out, int out_size)
{
    const float* node_features = (const float*)d_in[0];
    const float* edge_features = (const float*)d_in[1]; // [2, E, 4]
    const int*   src           = (const int*)d_in[2];
    const int*   dst           = (const int*)d_in[3];
    const float* W0            = (const float*)d_in[4];
    const float* b0            = (const float*)d_in[5];
    const float* W1            = (const float*)d_in[6];
    const float* b1            = (const float*)d_in[7];
    const float* Wfc           = (const float*)d_in[8];
    const float* bfc           = (const float*)d_in[9];
    float* out = (float*)d_out;

    uint4 *Pp;
    float *hp;
    int *cntp, *offp, *rkp;
    int2 *csrp;
    uint32_t *bhp, *blp;
    cudaGetSymbolAddress((void**)&Pp, g_P);
    cudaGetSymbolAddress((void**)&hp, g_h);
    cudaGetSymbolAddress((void**)&cntp, g_cnt);
    cudaGetSymbolAddress((void**)&offp, g_off);
    cudaGetSymbolAddress((void**)&rkp, g_rank);
    cudaGetSymbolAddress((void**)&csrp, g_csr);
    cudaGetSymbolAddress((void**)&bhp, g_Bhi);
    cudaGetSymbolAddress((void**)&blp, g_Blo);

    const int tc_smem = SM_TOT * (int)sizeof(uint32_t); // 108KB (>= stage 69.6KB)
    cudaFuncSetAttribute(gemm_tc_kernel, cudaFuncAttributeMaxDynamicSharedMemorySize, tc_smem);

    const int gemm_blocks = (NN + 127) / 128;
    const int layer_blocks = (NN + 7) / 8;   // 8 warps/block, warp per node

    const float4* cef0 = (const float4*)edge_features;
    const float4* cef1 = (const float4*)(edge_features + (size_t)EE * KK);

    // CSR build (dst shared by both layers) + W packing
    cudaMemsetAsync(cntp, 0, NN * sizeof(int), 0);
    hist_packW_kernel<<<(HPW_TOTAL + 255) / 256, 256>>>(dst, cntp, rkp, W0, W1, bhp, blp);
    scan_kernel<<<1, 1024>>>(cntp, offp, NN);
    scatter_kernel<<<(EE + 255) / 256, 256>>>(src, dst, offp, rkp, csrp, EE);

    // Layer 0
    gemm_tc_kernel<<<gemm_blocks, 256, tc_smem>>>(node_features, bhp, blp, Pp, NN);
    layer_kernel<<<layer_blocks, 256>>>(Pp, offp, cntp, csrp, cef0, b0, hp, NN);

    // Layer 1 + fused FC
    gemm_tc_kernel<<<gemm_blocks, 256, tc_smem>>>(hp, bhp + 8192, blp + 8192, Pp, NN);
    layer_fc_kernel<<<layer_blocks, 256>>>(Pp, offp, cntp, csrp, cef1, b1, Wfc, bfc, out, NN);
}

// round 17
// speedup vs baseline: 1.1516x; 1.0785x over previous
#include <cuda_runtime.h>
#include <cuda_bf16.h>
#include <cuda_fp16.h>
#include <cstdint>

// Problem constants (fixed by the dataset)
#define NN 50000
#define EE 500000
#define DD 64      // node feature dim (== hidden dim H)
#define KK 4       // edge feature dim
#define HH 64      // hidden
#define CC 40      // classes
#define PCOLS 256  // K*H

// ---------------------------------------------------------------------------
// Scratch (__device__ globals are the allowed scratch mechanism)
// P layout: per node, 32 x uint4. uint4 index h2 (=h/2) holds 4 half2s,
// one per k: entry [h2][k] = (P[k*64+2*h2], P[k*64+2*h2+1]).
// => lane l loads its whole per-edge operand as ONE uint4.
// ---------------------------------------------------------------------------
__device__ uint4 g_P[NN * 32];        // per-node P, (h-pair, k)-ordered fp16
__device__ float g_h[NN * HH];        // hidden node features between layers
__device__ int   g_cnt[NN];           // in-degree
__device__ int   g_off[NN];           // CSR row offsets (by dst)
__device__ int   g_rank[EE];          // within-dst rank of each edge
__device__ int2  g_csr[EE];           // (src, edge-id) per sorted slot
__device__ uint32_t g_Bf[2 * 8192];   // packed W (fp16 half2), [layer][n*32+dd]

// ---------------------------------------------------------------------------
// fp16 pair packing helper
// ---------------------------------------------------------------------------
__device__ __forceinline__ uint32_t pack_h2(float x, float y) {
    __half2 h = __floats2half2_rn(x, y);
    return *reinterpret_cast<uint32_t*>(&h);
}

// ---------------------------------------------------------------------------
// Fused: histogram of dst (records within-node rank) + W packing (fp16).
// ---------------------------------------------------------------------------
#define HPW_TOTAL (EE + 2 * 8192)
__global__ void hist_packW_kernel(
    const int* __restrict__ dst, int* __restrict__ cnt, int* __restrict__ rank,
    const float* __restrict__ W0, const float* __restrict__ W1,
    uint32_t* __restrict__ Bf)
{
    int t = blockIdx.x * blockDim.x + threadIdx.x;
    if (t < EE) {
        rank[t] = atomicAdd(&cnt[dst[t]], 1);
    } else if (t < HPW_TOTAL) {
        int idx = t - EE;                 // 0 .. 16383
        int l = idx >> 13;
        int r = idx & 8191;
        int n = r >> 5;
        int dd = r & 31;
        const float* W = l ? W1 : W0;
        int ke = n >> 6, h = n & 63;
        float x = W[(ke * 64 + 2 * dd) * 64 + h];
        float y = W[(ke * 64 + 2 * dd + 1) * 64 + h];
        Bf[idx] = pack_h2(x, y);
    }
}

// ---------------------------------------------------------------------------
// Exclusive prefix sum over cnt -> off. Single block, 1024 thr.
// ---------------------------------------------------------------------------
__global__ __launch_bounds__(1024) void scan_kernel(
    const int* __restrict__ cnt, int* __restrict__ off, int N)
{
    __shared__ int ts[1024];
    const int tid = threadIdx.x;
    const int CH = (N + 1023) / 1024;
    int b = tid * CH;
    int e = b + CH; if (e > N) e = N;
    int s = 0;
    for (int i = b; i < e; i++) s += cnt[i];
    ts[tid] = s;
    __syncthreads();
    for (int d = 1; d < 1024; d <<= 1) {
        int v = (tid >= d) ? ts[tid - d] : 0;
        __syncthreads();
        ts[tid] += v;
        __syncthreads();
    }
    int run = (tid == 0) ? 0 : ts[tid - 1];
    for (int i = b; i < e; i++) {
        off[i] = run;
        run += cnt[i];
    }
}

// ---------------------------------------------------------------------------
// Scatter (no atomics): slot = off[dst[e]] + rank[e]; write (src, e).
// ---------------------------------------------------------------------------
__global__ void scatter_kernel(
    const int* __restrict__ src, const int* __restrict__ dst,
    const int* __restrict__ off, const int* __restrict__ rank,
    int2* __restrict__ csr, int E)
{
    int e = blockIdx.x * blockDim.x + threadIdx.x;
    if (e >= E) return;
    int p = off[dst[e]] + rank[e];
    csr[p] = make_int2(src[e], e);
}

// ---------------------------------------------------------------------------
// Tensor-core GEMM: P[N,256] = A[N,64] @ B[64,256], PLAIN fp16 inputs
// (A and W quantized to fp16 — same magnitude as the fp16 P-storage error),
// fp32 accumulate. Output fp16 in (h-pair, k)-ordered layout, SMEM-staged
// coalesced epilogue.
// Block: 256 thr (8 warps), tile M=128, N=256. Warp tile 32x128.
// 128 MMAs/warp (3x fewer than the split-bf16 version).
// ---------------------------------------------------------------------------
#define GSTRIDE 36   // u32 row stride: rows shift 4 banks -> ldmatrix conflict-free
#define SM_A 0
#define SM_B (128 * GSTRIDE)
#define SM_MAIN ((128 + 256) * GSTRIDE)          // 13824 u32 = 55.3KB
#define SSTRIDE 136  // stage row stride in u32 (16B-aligned, 8-bank row shift)
#define SM_STAGE (128 * SSTRIDE)                 // 17408 u32 = 69.6KB
#define SM_TOT (SM_STAGE > SM_MAIN ? SM_STAGE : SM_MAIN)

__device__ __forceinline__ void ldsm_x4(uint32_t* r, uint32_t addr) {
    asm volatile("ldmatrix.sync.aligned.m8n8.x4.shared.b16 {%0,%1,%2,%3}, [%4];"
                 : "=r"(r[0]), "=r"(r[1]), "=r"(r[2]), "=r"(r[3]) : "r"(addr));
}

#define MMA_F16(C, A, B0, B1) asm volatile( \
    "mma.sync.aligned.m16n8k16.row.col.f32.f16.f16.f32 " \
    "{%0,%1,%2,%3}, {%4,%5,%6,%7}, {%8,%9}, {%0,%1,%2,%3};\n" \
    : "+f"((C)[0]), "+f"((C)[1]), "+f"((C)[2]), "+f"((C)[3]) \
    : "r"((A)[0]), "r"((A)[1]), "r"((A)[2]), "r"((A)[3]), "r"(B0), "r"(B1))

__global__ __launch_bounds__(256, 1) void gemm_tc_kernel(
    const float* __restrict__ A,
    const uint32_t* __restrict__ Bf_g,
    uint4* __restrict__ Pout, int Nrows)   // Pout: uint4 view, row stride 32
{
    extern __shared__ uint32_t smTC[];

    const int tid = threadIdx.x;
    const int row0 = blockIdx.x * 128;

    // Copy pre-packed B into smem (uint4)
    {
        const uint4* bf = reinterpret_cast<const uint4*>(Bf_g);
        #pragma unroll
        for (int it = 0; it < 8; it++) {
            int i = tid + it * 256;          // 0..2047, n = i>>3, c = i&7
            int n = i >> 3, c = i & 7;
            *reinterpret_cast<uint4*>(&smTC[SM_B + n * GSTRIDE + c * 4]) = bf[i];
        }
    }
    // Pack A tile (128 rows x 32 pairs) fp32 -> fp16
    #pragma unroll
    for (int it = 0; it < 16; it++) {
        int idx = tid + it * 256;            // 0..4095
        int row = idx >> 5;
        int dd = idx & 31;
        float2 v = make_float2(0.f, 0.f);
        if (row0 + row < Nrows)
            v = reinterpret_cast<const float2*>(A)[(size_t)(row0 + row) * 32 + dd];
        smTC[SM_A + row * GSTRIDE + dd] = pack_h2(v.x, v.y);
    }
    __syncthreads();

    const int w = tid >> 5;
    const int lane = tid & 31;
    const int g = lane >> 2;      // groupID
    const int ctid = lane & 3;    // thread in group
    const int wm = w >> 1;        // 0..3 -> row base wm*32
    const int wn = w & 1;         // 0..1 -> col base wn*128

    const uint32_t sb = (uint32_t)__cvta_generic_to_shared(smTC);
    const int aRow = wm * 32 + (lane & 15);
    const int aCol = (lane >> 4) << 2;
    const uint32_t aBase = sb + (SM_A + aRow * GSTRIDE + aCol) * 4;
    const int bRow = wn * 128 + ((lane >> 4) << 3) + (lane & 7);
    const int bCol = ((lane >> 3) & 1) << 2;
    const uint32_t bBase = sb + (SM_B + bRow * GSTRIDE + bCol) * 4;

    float acc[2][16][4];
    #pragma unroll
    for (int mt = 0; mt < 2; mt++)
        #pragma unroll
        for (int nt = 0; nt < 16; nt++)
            #pragma unroll
            for (int q = 0; q < 4; q++) acc[mt][nt][q] = 0.f;

    #pragma unroll
    for (int ks = 0; ks < 4; ks++) {
        const uint32_t koff = ks * 8 * 4;
        uint32_t ah[2][4];
        ldsm_x4(ah[0], aBase + koff);
        ldsm_x4(ah[1], aBase + 16 * GSTRIDE * 4 + koff);
        #pragma unroll
        for (int nt2 = 0; nt2 < 8; nt2++) {
            uint32_t bh[4];
            ldsm_x4(bh, bBase + nt2 * 16 * GSTRIDE * 4 + koff);
            #pragma unroll
            for (int mt = 0; mt < 2; mt++) {
                MMA_F16(acc[mt][2 * nt2],     ah[mt], bh[0], bh[1]);
                MMA_F16(acc[mt][2 * nt2 + 1], ah[mt], bh[2], bh[3]);
            }
        }
    }

    // Epilogue: stage permuted half2s in smem (reuse smTC), then coalesced
    // uint4 row stores to global.
    __syncthreads();   // done reading A/B tiles
    #pragma unroll
    for (int mt = 0; mt < 2; mt++) {
        #pragma unroll
        for (int nt = 0; nt < 16; nt++) {
            int rloc = wm * 32 + mt * 16 + g;
            int col = wn * 128 + nt * 8 + 2 * ctid;  // 0..255, even
            int ke = col >> 6;
            int h2 = (col & 63) >> 1;
            int pidx = h2 * 4 + ke;
            smTC[rloc * SSTRIDE + pidx] = pack_h2(acc[mt][nt][0], acc[mt][nt][1]);
            smTC[(rloc + 8) * SSTRIDE + pidx] = pack_h2(acc[mt][nt][2], acc[mt][nt][3]);
        }
    }
    __syncthreads();
    // Coalesced copy out: 128 rows x 32 uint4
    #pragma unroll
    for (int it = 0; it < 16; it++) {
        int i = tid + it * 256;          // 0..4095
        int r = i >> 5, c = i & 31;
        if (row0 + r < Nrows)
            Pout[(size_t)(row0 + r) * 32 + c] =
                *reinterpret_cast<uint4*>(&smTC[r * SSTRIDE + c * 4]);
    }
}

// ---------------------------------------------------------------------------
// Consumer: warp = node, lane owns 2 h-cols (h = 2*lane, 2*lane+1).
// Per edge: 1 uniform csr load + 1 uniform ev load + ONE uint4 P load/lane.
// fp32 message math (R14 known-good). Unroll-8 with all loads hoisted.
// ---------------------------------------------------------------------------
__device__ __forceinline__ void edge_fma(
    float4 ev, uint4 pk, float2 b2, float& ax, float& ay)
{
    const __half2* h2p = reinterpret_cast<const __half2*>(&pk);
    float2 p0 = __half22float2(h2p[0]);   // k=0
    float2 p1 = __half22float2(h2p[1]);   // k=1
    float2 p2 = __half22float2(h2p[2]);   // k=2
    float2 p3 = __half22float2(h2p[3]);   // k=3
    float vx = b2.x + ev.x * p0.x + ev.y * p1.x + ev.z * p2.x + ev.w * p3.x;
    float vy = b2.y + ev.x * p0.y + ev.y * p1.y + ev.z * p2.y + ev.w * p3.y;
    ax += fmaxf(vx, 0.f);
    ay += fmaxf(vy, 0.f);
}

__device__ __forceinline__ void consume_node(
    const uint4* __restrict__ P, const int2* __restrict__ csr,
    const float4* __restrict__ cef, int o, int deg, int lane,
    float2 b2, float& rx, float& ry)
{
    float ax = 0.f, ay = 0.f;
    int j = 0;
    for (; j + 8 <= deg; j += 8) {
        int2 c[8];
        #pragma unroll
        for (int q = 0; q < 8; q++) c[q] = csr[o + j + q];
        float4 ev[8];
        uint4 p[8];
        #pragma unroll
        for (int q = 0; q < 8; q++) ev[q] = cef[c[q].y];
        #pragma unroll
        for (int q = 0; q < 8; q++) p[q] = P[(size_t)c[q].x * 32 + lane];
        #pragma unroll
        for (int q = 0; q < 8; q++) edge_fma(ev[q], p[q], b2, ax, ay);
    }
    for (; j + 4 <= deg; j += 4) {
        int2 c[4];
        #pragma unroll
        for (int q = 0; q < 4; q++) c[q] = csr[o + j + q];
        float4 ev[4];
        uint4 p[4];
        #pragma unroll
        for (int q = 0; q < 4; q++) ev[q] = cef[c[q].y];
        #pragma unroll
        for (int q = 0; q < 4; q++) p[q] = P[(size_t)c[q].x * 32 + lane];
        #pragma unroll
        for (int q = 0; q < 4; q++) edge_fma(ev[q], p[q], b2, ax, ay);
    }
    for (; j < deg; j++) {
        int2 c = csr[o + j];
        float4 ev = cef[c.y];
        uint4 p = P[(size_t)c.x * 32 + lane];
        edge_fma(ev, p, b2, ax, ay);
    }
    float inv = 1.0f / fmaxf((float)deg, 1.0f);
    rx = fmaxf(ax * inv, 0.f);
    ry = fmaxf(ay * inv, 0.f);
}

// ---------------------------------------------------------------------------
// Layer consumer: h = relu(mean(messages)). One warp per node.
// ---------------------------------------------------------------------------
__global__ __launch_bounds__(256) void layer_kernel(
    const uint4* __restrict__ P, const int* __restrict__ off,
    const int* __restrict__ cnt, const int2* __restrict__ csr,
    const float4* __restrict__ cef, const float* __restrict__ bias,
    float* __restrict__ hout, int N)
{
    int warp = (blockIdx.x * blockDim.x + threadIdx.x) >> 5;
    int lane = threadIdx.x & 31;
    if (warp >= N) return;
    float2 b2 = reinterpret_cast<const float2*>(bias)[lane];
    float rx, ry;
    consume_node(P, csr, cef, off[warp], cnt[warp], lane, b2, rx, ry);
    reinterpret_cast<float2*>(hout)[(size_t)warp * 32 + lane] = make_float2(rx, ry);
}

// ---------------------------------------------------------------------------
// Layer-2 consumer fused with final FC: out[n] = h2[n] @ Wfc + bfc
// ---------------------------------------------------------------------------
__global__ __launch_bounds__(256) void layer_fc_kernel(
    const uint4* __restrict__ P, const int* __restrict__ off,
    const int* __restrict__ cnt, const int2* __restrict__ csr,
    const float4* __restrict__ cef, const float* __restrict__ bias,
    const float* __restrict__ Wfc, const float* __restrict__ bfc,
    float* __restrict__ out, int N)
{
    __shared__ float Wf[64 * 40];
    __shared__ float bf[40];
    __shared__ float hrow[8][64];

    const int tid = threadIdx.x;
    for (int i = tid; i < 64 * 40; i += 256) Wf[i] = Wfc[i];
    if (tid < 40) bf[tid] = bfc[tid];
    __syncthreads();

    const int wwarp = tid >> 5;
    const int lane = tid & 31;
    const int n = blockIdx.x * 8 + wwarp;

    float rx = 0.f, ry = 0.f;
    if (n < N) {
        float2 b2 = reinterpret_cast<const float2*>(bias)[lane];
        consume_node(P, csr, cef, off[n], cnt[n], lane, b2, rx, ry);
    }
    hrow[wwarp][2 * lane] = rx;
    hrow[wwarp][2 * lane + 1] = ry;
    __syncwarp();

    if (n < N) {
        float a0 = bf[lane];
        float a1 = (lane < 8) ? bf[32 + lane] : 0.f;
        #pragma unroll
        for (int h = 0; h < 64; h++) {
            float hv = hrow[wwarp][h];
            a0 += hv * Wf[h * 40 + lane];
            if (lane < 8) a1 += hv * Wf[h * 40 + 32 + lane];
        }
        out[(size_t)n * 40 + lane] = a0;
        if (lane < 8) out[(size_t)n * 40 + 32 + lane] = a1;
    }
}

// ---------------------------------------------------------------------------
extern "C" void kernel_launch(void* const* d_in, const int* in_sizes, int n_in,
                              void* d_out, int out_size)
{
    const float* node_features = (const float*)d_in[0];
    const float* edge_features = (const float*)d_in[1]; // [2, E, 4]
    const int*   src           = (const int*)d_in[2];
    const int*   dst           = (const int*)d_in[3];
    const float* W0            = (const float*)d_in[4];
    const float* b0            = (const float*)d_in[5];
    const float* W1            = (const float*)d_in[6];
    const float* b1            = (const float*)d_in[7];
    const float* Wfc           = (const float*)d_in[8];
    const float* bfc           = (const float*)d_in[9];
    float* out = (float*)d_out;

    uint4 *Pp;
    float *hp;
    int *cntp, *offp, *rkp;
    int2 *csrp;
    uint32_t *bfp;
    cudaGetSymbolAddress((void**)&Pp, g_P);
    cudaGetSymbolAddress((void**)&hp, g_h);
    cudaGetSymbolAddress((void**)&cntp, g_cnt);
    cudaGetSymbolAddress((void**)&offp, g_off);
    cudaGetSymbolAddress((void**)&rkp, g_rank);
    cudaGetSymbolAddress((void**)&csrp, g_csr);
    cudaGetSymbolAddress((void**)&bfp, g_Bf);

    const int tc_smem = SM_TOT * (int)sizeof(uint32_t); // 69.6KB
    cudaFuncSetAttribute(gemm_tc_kernel, cudaFuncAttributeMaxDynamicSharedMemorySize, tc_smem);

    const int gemm_blocks = (NN + 127) / 128;
    const int layer_blocks = (NN + 7) / 8;   // 8 warps/block, warp per node

    const float4* cef0 = (const float4*)edge_features;
    const float4* cef1 = (const float4*)(edge_features + (size_t)EE * KK);

    // CSR build (dst shared by both layers) + W packing
    cudaMemsetAsync(cntp, 0, NN * sizeof(int), 0);
    hist_packW_kernel<<<(HPW_TOTAL + 255) / 256, 256>>>(dst, cntp, rkp, W0, W1, bfp);
    scan_kernel<<<1, 1024>>>(cntp, offp, NN);
    scatter_kernel<<<(EE + 255) / 256, 256>>>(src, dst, offp, rkp, csrp, EE);

    // Layer 0
    gemm_tc_kernel<<<gemm_blocks, 256, tc_smem>>>(node_features, bfp, Pp, NN);
    layer_kernel<<<layer_blocks, 256>>>(Pp, offp, cntp, csrp, cef0, b0, hp, NN);

    // Layer 1 + fused FC
    gemm_tc_kernel<<<gemm_blocks, 256, tc_smem>>>(hp, bfp + 8192, Pp, NN);
    layer_fc_kernel<<<layer_blocks, 256>>>(Pp, offp, cntp, csrp, cef1, b1, Wfc, bfc, out, NN);
}